// round 13
// baseline (speedup 1.0000x reference)
#include <cuda_runtime.h>
#include <cstdint>
#include <cfloat>

#define BHn   64
#define TQn   1024
#define TKn   1024
#define DKn   64
#define QT    32
#define NTHR  256     // 8 warps, both kernels
#define KST   68      // K/V tile row stride (68%32=4 -> conflict-free)
#define SCST  1028    // score row stride
#define WST   132     // K2 weight tile row stride (132%32=4)

// ---- K1 smem: qsh[32][68] | kvsh[2][128][68] | scsh[32][1028] | mbias[1024] | invsh[32]
#define QSH_F   (QT*KST)                  // 2176
#define KVSH_F  (256*KST)                 // 17408 (two 128-row buffers)
#define SCSH_F  (QT*SCST)                 // 32896
#define SMEM1_F (QSH_F + KVSH_F + SCSH_F + TKn + 32)
#define SMEM1_B (SMEM1_F * 4)             // ~214 KB -> 1 block/SM

// ---- K2 smem: wsh[2][32][132] | vsh[2][128][68]
#define WSH_F   (32*WST)                  // 4224 per buffer
#define VSH_F   (128*KST)                 // 8704 per buffer
#define SMEM2_F (2*WSH_F + 2*VSH_F)       // 25856
#define SMEM2_B (SMEM2_F * 4)             // 103424 B -> 2 blocks/SM

// ---------------------------------------------------------------------------
__device__ int g_mask_narrow;

__global__ void detect_mask_kernel(const unsigned int* __restrict__ mw) {
    __shared__ int found;
    if (threadIdx.x == 0) found = 0;
    __syncthreads();
    int local = 0;
    for (int i = threadIdx.x; i < (BHn * TKn) / 4; i += blockDim.x) {
        if (mw[i] & 0xFFFFFF00u) local = 1;
    }
    if (local) atomicOr(&found, 1);
    __syncthreads();
    if (threadIdx.x == 0) g_mask_narrow = found;
}

// packed dual-fp32 FMA (ptxas never emits FFMA2 from C++)
__device__ __forceinline__ float2 ffma2(float2 a, float2 b, float2 c) {
    float2 d;
    asm("fma.rn.f32x2 %0, %1, %2, %3;"
        : "=l"(reinterpret_cast<unsigned long long&>(d))
        : "l"(reinterpret_cast<unsigned long long&>(a)),
          "l"(reinterpret_cast<unsigned long long&>(b)),
          "l"(reinterpret_cast<unsigned long long&>(c)));
    return d;
}

__device__ __forceinline__ unsigned int smem_u32(const void* p) {
    return (unsigned int)__cvta_generic_to_shared(p);
}
__device__ __forceinline__ void cp16(unsigned int dst, const void* src) {
    asm volatile("cp.async.cg.shared.global [%0], [%1], 16;" :: "r"(dst), "l"(src));
}
__device__ __forceinline__ void cp_commit() {
    asm volatile("cp.async.commit_group;");
}
__device__ __forceinline__ void cp_wait1() {
    asm volatile("cp.async.wait_group 1;" ::: "memory");
}
__device__ __forceinline__ void cp_wait0() {
    asm volatile("cp.async.wait_group 0;" ::: "memory");
}

// stage a 128x64 float tile (2048 float4) into smem at stride KST; 8 f4/thread
__device__ __forceinline__ void stage128(unsigned int dst_u32, const float4* __restrict__ g, int t) {
    #pragma unroll
    for (int i = 0; i < 8; i++) {
        int idx = t + i * NTHR;
        int r = idx >> 4, c4 = idx & 15;
        cp16(dst_u32 + (unsigned int)(r * KST + 4 * c4) * 4u, g + idx);
    }
    cp_commit();
}

// ===========================================================================
// K1: scores = QK^T/8 + mask -> softmax -> normalized weights to global
// one block = 32 queries x one bh head, 8 warps, double-buffered K tiles
// ===========================================================================
extern "C" __global__ void __launch_bounds__(NTHR, 1)
attn_scores_kernel(const float* __restrict__ Q, const float* __restrict__ K,
                   const unsigned char* __restrict__ Mb,
                   const int* __restrict__ pHA, const int* __restrict__ pNH,
                   float* __restrict__ Wout)
{
    extern __shared__ float sm[];
    float* qsh   = sm;                       // [32][KST]
    float* kvsh  = sm + QSH_F;               // [2][128][KST]
    float* scsh  = kvsh + KVSH_F;            // [32][SCST]
    float* mbias = scsh + SCSH_F;            // [1024]
    float* invsh = mbias + TKn;              // [32]

    const int t  = threadIdx.x;
    const int w  = t >> 5;                   // warp 0..7
    const int l  = t & 31;
    const int bh = blockIdx.y;
    const int q0 = blockIdx.x * QT;

    float* wrow_base = Wout + ((size_t)bh * TQn + q0) * TKn;

    // ---- head ablation: weights exactly zero, done ----
    if (pNH[0] > 0 && (bh % pNH[0]) == pHA[0]) {
        float4 z = make_float4(0.f, 0.f, 0.f, 0.f);
        float4* w4 = (float4*)wrow_base;
        #pragma unroll 4
        for (int i = t; i < QT * TKn / 4; i += NTHR) w4[i] = z;
        return;
    }

    const int shift = g_mask_narrow ? 0 : 2;
    const unsigned char* mrow = Mb + (((size_t)bh * TKn) << shift);
    const float4* Kg = (const float4*)(K + ((size_t)bh * TKn) * DKn);
    const unsigned int kv0 = smem_u32(kvsh);
    const unsigned int kv1 = smem_u32(kvsh + 128 * KST);

    // prestage K tiles 0 and 1
    stage128(kv0, Kg, t);
    stage128(kv1, Kg + 128 * 16, t);

    // mask bias + Q tile
    #pragma unroll
    for (int i = 0; i < 4; i++) {
        int k = t + i * NTHR;
        mbias[k] = mrow[(size_t)k << shift] ? 0.f : -FLT_MAX;
    }
    {
        const float4* Qg = (const float4*)(Q + ((size_t)bh * TQn + q0) * DKn);
        #pragma unroll
        for (int i = 0; i < 2; i++) {
            int idx = t + i * NTHR;
            int r = idx >> 4, c4 = idx & 15;
            *(float4*)&qsh[r * KST + 4 * c4] = Qg[idx];
        }
    }

    // Phase A: warp owns k rows [16w,16w+16) of each 128-row tile.
    // lane: qg=l>>2 (0..7) -> q rows qg+8i (i<4); kg=l&3 -> k rows kg+4j (j<4)
    const int qg = l >> 2;
    const int kg = l & 3;

    for (int kt = 0; kt < 8; kt++) {
        if (kt < 7) cp_wait1(); else cp_wait0();
        __syncthreads();                      // tile kt resident, prior buf reuse safe

        const float* kb_sh = &kvsh[(kt & 1) * 128 * KST + (16 * w + kg) * KST];

        float2 acc[4][4];
        #pragma unroll
        for (int i = 0; i < 4; i++)
            #pragma unroll
            for (int j = 0; j < 4; j++) acc[i][j] = make_float2(0.f, 0.f);

        #pragma unroll 4
        for (int d4 = 0; d4 < 16; d4++) {
            float4 kv[4];
            #pragma unroll
            for (int j = 0; j < 4; j++)
                kv[j] = *(const float4*)&kb_sh[4 * j * KST + 4 * d4];
            #pragma unroll
            for (int i = 0; i < 4; i++) {
                float4 qv = *(const float4*)&qsh[(qg + 8 * i) * KST + 4 * d4];
                #pragma unroll
                for (int j = 0; j < 4; j++) {
                    acc[i][j] = ffma2(make_float2(qv.x, qv.y), make_float2(kv[j].x, kv[j].y), acc[i][j]);
                    acc[i][j] = ffma2(make_float2(qv.z, qv.w), make_float2(kv[j].z, kv[j].w), acc[i][j]);
                }
            }
        }

        __syncthreads();                      // all warps done with this buffer
        if (kt < 6) stage128((kt & 1) ? kv1 : kv0, Kg + (size_t)(kt + 2) * 128 * 16, t);

        const int kb = kt * 128 + 16 * w;
        #pragma unroll
        for (int i = 0; i < 4; i++)
            #pragma unroll
            for (int j = 0; j < 4; j++)
                scsh[(qg + 8 * i) * SCST + kb + kg + 4 * j] = acc[i][j].x + acc[i][j].y;
    }
    __syncthreads();

    // softmax: warp w handles rows 4w..4w+3; scale + mask bias fused
    #pragma unroll
    for (int rr = 0; rr < 4; rr++) {
        int r = 4 * w + rr;
        float* row = &scsh[r * SCST];

        float mx = -FLT_MAX;
        #pragma unroll
        for (int i = 0; i < 8; i++) {
            float4 x = *(const float4*)&row[4 * l + 128 * i];
            float4 b = *(const float4*)&mbias[4 * l + 128 * i];
            x.x = fmaf(x.x, 0.125f, b.x);
            x.y = fmaf(x.y, 0.125f, b.y);
            x.z = fmaf(x.z, 0.125f, b.z);
            x.w = fmaf(x.w, 0.125f, b.w);
            *(float4*)&row[4 * l + 128 * i] = x;
            mx = fmaxf(mx, fmaxf(fmaxf(x.x, x.y), fmaxf(x.z, x.w)));
        }
        #pragma unroll
        for (int off = 16; off > 0; off >>= 1)
            mx = fmaxf(mx, __shfl_xor_sync(0xffffffffu, mx, off));

        float s = 0.f;
        #pragma unroll
        for (int i = 0; i < 8; i++) {
            float4 x = *(const float4*)&row[4 * l + 128 * i];
            x.x = __expf(x.x - mx);
            x.y = __expf(x.y - mx);
            x.z = __expf(x.z - mx);
            x.w = __expf(x.w - mx);
            *(float4*)&row[4 * l + 128 * i] = x;
            s += (x.x + x.y) + (x.z + x.w);
        }
        #pragma unroll
        for (int off = 16; off > 0; off >>= 1)
            s += __shfl_xor_sync(0xffffffffu, s, off);

        if (l == 0) invsh[r] = (mx == -FLT_MAX) ? 0.f : __frcp_rn(s);
    }
    __syncthreads();

    // normalized weights -> global (coalesced float4)
    {
        float4* w4 = (float4*)wrow_base;
        #pragma unroll
        for (int i = 0; i < 32; i++) {
            int j  = t + i * NTHR;            // 0..8191
            int r  = j >> 8;
            int c4 = j & 255;
            float inv = invsh[r];
            float4 e = *(const float4*)&scsh[r * SCST + 4 * c4];
            e.x *= inv; e.y *= inv; e.z *= inv; e.w *= inv;
            w4[r * 256 + c4] = e;
        }
    }
}

// ===========================================================================
// K2: O = W @ V   (W already normalized; ablated/fully-masked rows are 0)
// one block = 32 queries x one bh head, 8 warps, 2 blocks/SM, double-buffered
// ===========================================================================
extern "C" __global__ void __launch_bounds__(NTHR, 2)
attn_out_kernel(const float* __restrict__ V, const float* __restrict__ W,
                float* __restrict__ O)
{
    extern __shared__ float sm[];
    float* wsh = sm;                          // [2][32][WST]
    float* vsh = sm + 2 * WSH_F;              // [2][128][KST] (reused for reduction)

    const int t  = threadIdx.x;
    const int w  = t >> 5;
    const int l  = t & 31;
    const int bh = blockIdx.y;
    const int q0 = blockIdx.x * QT;

    const float4* Vg = (const float4*)(V + ((size_t)bh * TKn) * DKn);
    const float4* Wg = (const float4*)(W + ((size_t)bh * TQn + q0) * TKn);
    float* orow_base = O + ((size_t)bh * TQn + q0) * DKn;

    const unsigned int wsh_u = smem_u32(wsh);
    const unsigned int vsh_u = smem_u32(vsh);

    // stage one tile (W 32x128 + V 128x64) into buffer b
    auto stage = [&](int b, int kt) {
        unsigned int wd = wsh_u + (unsigned int)(b * WSH_F) * 4u;
        #pragma unroll
        for (int i = 0; i < 4; i++) {
            int idx = t + i * NTHR;           // 0..1023 : W f4
            int r = idx >> 5, c4 = idx & 31;
            cp16(wd + (unsigned int)(r * WST + 4 * c4) * 4u, Wg + (size_t)r * 256 + kt * 32 + c4);
        }
        unsigned int vd = vsh_u + (unsigned int)(b * VSH_F) * 4u;
        #pragma unroll
        for (int i = 0; i < 8; i++) {
            int idx = t + i * NTHR;           // 0..2047 : V f4
            int r = idx >> 4, c4 = idx & 15;
            cp16(vd + (unsigned int)(r * KST + 4 * c4) * 4u, Vg + (size_t)(kt * 128 + r) * 16 + c4);
        }
        cp_commit();
    };

    stage(0, 0);
    stage(1, 1);

    // warp owns k rows [16w,16w+16) per tile; lane: qg2=l>>3 -> q rows qg2+4i (i<8);
    // dg=l&7 -> d floats [8dg,8dg+8)
    const int qg2 = l >> 3;
    const int dg  = l & 7;

    float2 acc2[8][4];
    #pragma unroll
    for (int i = 0; i < 8; i++)
        #pragma unroll
        for (int c = 0; c < 4; c++) acc2[i][c] = make_float2(0.f, 0.f);

    for (int kt = 0; kt < 8; kt++) {
        if (kt < 7) cp_wait1(); else cp_wait0();
        __syncthreads();

        const float* vb = &vsh[(kt & 1) * VSH_F];
        const float* wb = &wsh[(kt & 1) * WSH_F];

        #pragma unroll 2
        for (int g4 = 0; g4 < 4; g4++) {
            float4 v[4][2];
            #pragma unroll
            for (int kk = 0; kk < 4; kk++) {
                const float* vr = &vb[(16 * w + 4 * g4 + kk) * KST + 8 * dg];
                v[kk][0] = *(const float4*)&vr[0];
                v[kk][1] = *(const float4*)&vr[4];
            }
            #pragma unroll
            for (int i = 0; i < 8; i++) {
                float4 wf = *(const float4*)&wb[(qg2 + 4 * i) * WST + 16 * w + 4 * g4];
                acc2[i][0] = ffma2(make_float2(wf.x, wf.x), make_float2(v[0][0].x, v[0][0].y), acc2[i][0]);
                acc2[i][1] = ffma2(make_float2(wf.x, wf.x), make_float2(v[0][0].z, v[0][0].w), acc2[i][1]);
                acc2[i][2] = ffma2(make_float2(wf.x, wf.x), make_float2(v[0][1].x, v[0][1].y), acc2[i][2]);
                acc2[i][3] = ffma2(make_float2(wf.x, wf.x), make_float2(v[0][1].z, v[0][1].w), acc2[i][3]);

                acc2[i][0] = ffma2(make_float2(wf.y, wf.y), make_float2(v[1][0].x, v[1][0].y), acc2[i][0]);
                acc2[i][1] = ffma2(make_float2(wf.y, wf.y), make_float2(v[1][0].z, v[1][0].w), acc2[i][1]);
                acc2[i][2] = ffma2(make_float2(wf.y, wf.y), make_float2(v[1][1].x, v[1][1].y), acc2[i][2]);
                acc2[i][3] = ffma2(make_float2(wf.y, wf.y), make_float2(v[1][1].z, v[1][1].w), acc2[i][3]);

                acc2[i][0] = ffma2(make_float2(wf.z, wf.z), make_float2(v[2][0].x, v[2][0].y), acc2[i][0]);
                acc2[i][1] = ffma2(make_float2(wf.z, wf.z), make_float2(v[2][0].z, v[2][0].w), acc2[i][1]);
                acc2[i][2] = ffma2(make_float2(wf.z, wf.z), make_float2(v[2][1].x, v[2][1].y), acc2[i][2]);
                acc2[i][3] = ffma2(make_float2(wf.z, wf.z), make_float2(v[2][1].z, v[2][1].w), acc2[i][3]);

                acc2[i][0] = ffma2(make_float2(wf.w, wf.w), make_float2(v[3][0].x, v[3][0].y), acc2[i][0]);
                acc2[i][1] = ffma2(make_float2(wf.w, wf.w), make_float2(v[3][0].z, v[3][0].w), acc2[i][1]);
                acc2[i][2] = ffma2(make_float2(wf.w, wf.w), make_float2(v[3][1].x, v[3][1].y), acc2[i][2]);
                acc2[i][3] = ffma2(make_float2(wf.w, wf.w), make_float2(v[3][1].z, v[3][1].w), acc2[i][3]);
            }
        }

        __syncthreads();
        if (kt < 6) stage(kt & 1, kt + 2);
    }

    // cross-warp k reduction via vsh (8 partials of [32][KST])
    {
        float* part = &vsh[w * (32 * KST)];
        #pragma unroll
        for (int i = 0; i < 8; i++) {
            float* p = &part[(qg2 + 4 * i) * KST + 8 * dg];
            *(float2*)&p[0] = acc2[i][0];
            *(float2*)&p[2] = acc2[i][1];
            *(float2*)&p[4] = acc2[i][2];
            *(float2*)&p[6] = acc2[i][3];
        }
    }
    __syncthreads();
    #pragma unroll
    for (int it = 0; it < 8; it++) {
        int idx = t + it * NTHR;              // 0..2047
        int q = idx >> 6, d = idx & 63;
        float s = 0.f;
        #pragma unroll
        for (int kk = 0; kk < 8; kk++)
            s += vsh[kk * (32 * KST) + q * KST + d];
        orow_base[(size_t)q * DKn + d] = s;
    }
}

// ---------------------------------------------------------------------------
extern "C" void kernel_launch(void* const* d_in, const int* in_sizes, int n_in,
                              void* d_out, int out_size) {
    const float*         Q  = (const float*)d_in[0];
    const float*         K  = (const float*)d_in[1];
    const float*         V  = (const float*)d_in[2];
    const unsigned char* Mb = (const unsigned char*)d_in[3];
    const int*           HA = (const int*)d_in[4];
    const int*           NH = (const int*)d_in[5];
    float*               O  = (float*)d_out;
    float*               W  = O + (size_t)BHn * TQn * DKn;

    cudaFuncSetAttribute(attn_scores_kernel,
                         cudaFuncAttributeMaxDynamicSharedMemorySize, SMEM1_B);
    cudaFuncSetAttribute(attn_out_kernel,
                         cudaFuncAttributeMaxDynamicSharedMemorySize, SMEM2_B);

    detect_mask_kernel<<<1, 256>>>((const unsigned int*)Mb);

    dim3 grid(TQn / QT, BHn);
    attn_scores_kernel<<<grid, NTHR, SMEM1_B>>>(Q, K, Mb, HA, NH, W);
    attn_out_kernel<<<grid, NTHR, SMEM2_B>>>(V, W, O);
}

// round 15
// speedup vs baseline: 1.6525x; 1.6525x over previous
#include <cuda_runtime.h>
#include <cuda_bf16.h>
#include <cstdint>
#include <cfloat>

#define BHn 64
#define TQn 1024
#define TKn 1024
#define DKn 64
#define SCST 1028
#define MB_NEG -30000.0f

__device__ __nv_bfloat16 g_Qh[BHn*TQn*DKn], g_Ql[BHn*TQn*DKn];
__device__ __nv_bfloat16 g_Kh[BHn*TKn*DKn], g_Kl[BHn*TKn*DKn];
__device__ __nv_bfloat16 g_VTh[BHn*DKn*TKn], g_VTl[BHn*DKn*TKn];
__device__ int g_mask_narrow;

// ---------------- helpers ----------------
__device__ __forceinline__ unsigned su32(const void* p){ return (unsigned)__cvta_generic_to_shared(p); }
__device__ __forceinline__ void cp16(unsigned d, const void* s){ asm volatile("cp.async.cg.shared.global [%0], [%1], 16;" :: "r"(d), "l"(s)); }
#define CPC()  asm volatile("cp.async.commit_group;")
#define CPW0() asm volatile("cp.async.wait_group 0;" ::: "memory")
#define CPW1() asm volatile("cp.async.wait_group 1;" ::: "memory")

__device__ __forceinline__ void ldm4(unsigned* r, unsigned a){
    asm volatile("ldmatrix.sync.aligned.m8n8.x4.shared.b16 {%0,%1,%2,%3}, [%4];"
        : "=r"(r[0]),"=r"(r[1]),"=r"(r[2]),"=r"(r[3]) : "r"(a));
}
__device__ __forceinline__ void ldm2(unsigned* r, unsigned a){
    asm volatile("ldmatrix.sync.aligned.m8n8.x2.shared.b16 {%0,%1}, [%2];"
        : "=r"(r[0]),"=r"(r[1]) : "r"(a));
}
__device__ __forceinline__ void mma16816(float* c, const unsigned* a, const unsigned* b){
    asm volatile("mma.sync.aligned.m16n8k16.row.col.f32.bf16.bf16.f32 "
        "{%0,%1,%2,%3}, {%4,%5,%6,%7}, {%8,%9}, {%0,%1,%2,%3};"
        : "+f"(c[0]),"+f"(c[1]),"+f"(c[2]),"+f"(c[3])
        : "r"(a[0]),"r"(a[1]),"r"(a[2]),"r"(a[3]), "r"(b[0]),"r"(b[1]));
}

// ---------------- prep kernels ----------------
__global__ void detect_mask_kernel(const unsigned int* __restrict__ mw) {
    __shared__ int found;
    if (threadIdx.x == 0) found = 0;
    __syncthreads();
    int local = 0;
    for (int i = threadIdx.x; i < (BHn * TKn) / 4; i += blockDim.x)
        if (mw[i] & 0xFFFFFF00u) local = 1;
    if (local) atomicOr(&found, 1);
    __syncthreads();
    if (threadIdx.x == 0) g_mask_narrow = found;
}

__global__ void split_qk_kernel(const float* __restrict__ Q, const float* __restrict__ K) {
    int n = BHn * TQn * DKn;
    for (int i = blockIdx.x * blockDim.x + threadIdx.x; i < n; i += gridDim.x * blockDim.x) {
        float q = Q[i]; __nv_bfloat16 h = __float2bfloat16(q);
        g_Qh[i] = h; g_Ql[i] = __float2bfloat16(q - __bfloat162float(h));
        float k = K[i]; h = __float2bfloat16(k);
        g_Kh[i] = h; g_Kl[i] = __float2bfloat16(k - __bfloat162float(h));
    }
}

__global__ void transpose_v_kernel(const float* __restrict__ V) {
    __shared__ float tile[32][33];
    int bh = blockIdx.z, k0 = blockIdx.x * 32, d0 = blockIdx.y * 32;
    const float* Vb = V + (size_t)bh * TKn * DKn;
    for (int r = threadIdx.y; r < 32; r += 8)
        tile[r][threadIdx.x] = Vb[(size_t)(k0 + r) * DKn + d0 + threadIdx.x];
    __syncthreads();
    for (int r = threadIdx.y; r < 32; r += 8) {
        float v = tile[threadIdx.x][r];
        __nv_bfloat16 h = __float2bfloat16(v);
        size_t o = (size_t)bh * DKn * TKn + (size_t)(d0 + r) * TKn + k0 + threadIdx.x;
        g_VTh[o] = h; g_VTl[o] = __float2bfloat16(v - __bfloat162float(h));
    }
}

// ============ K1: scores (mma bf16 split) -> softmax -> normalized W ============
// smem bytes: QH 0 (4608) | QL 4608 | K: 9216 + buf*36864 (hi 18432, lo +18432)
//             SC 82944 (32*1028*4) | MB 214528 | INV 218624 | total 218752
#define S1_QH 0
#define S1_QL 4608
#define S1_KB 9216
#define S1_SC 82944
#define S1_MB 214528
#define S1_INV 218624
#define SMEM1 218752

__device__ __forceinline__ void k1_stage_k(unsigned sb, const __nv_bfloat16* kh,
                                           const __nv_bfloat16* kl, int kt, int buf, int t) {
    unsigned base = sb + S1_KB + buf * 36864;
    const __nv_bfloat16* sh = kh + (size_t)kt * 128 * 64;
    const __nv_bfloat16* sl = kl + (size_t)kt * 128 * 64;
    #pragma unroll
    for (int i = 0; i < 4; i++) {
        int idx = t + i * 256, r = idx >> 3, c = idx & 7;
        cp16(base + r * 144 + c * 16, sh + (size_t)r * 64 + c * 8);
        cp16(base + 18432 + r * 144 + c * 16, sl + (size_t)r * 64 + c * 8);
    }
    CPC();
}

extern "C" __global__ void __launch_bounds__(256, 1)
attn_qk_kernel(const unsigned char* __restrict__ Mb, const int* __restrict__ pHA,
               const int* __restrict__ pNH, float* __restrict__ Wout)
{
    extern __shared__ char sm[];
    float* scsh = (float*)(sm + S1_SC);
    float* mb   = (float*)(sm + S1_MB);
    float* invsh = (float*)(sm + S1_INV);

    const int t = threadIdx.x, w = t >> 5, l = t & 31;
    const int bh = blockIdx.y, q0 = blockIdx.x * 32;
    float* wbase = Wout + ((size_t)bh * TQn + q0) * TKn;

    if (pNH[0] > 0 && (bh % pNH[0]) == pHA[0]) {
        float4 z = make_float4(0.f, 0.f, 0.f, 0.f);
        float4* w4 = (float4*)wbase;
        #pragma unroll 4
        for (int i = t; i < 32 * TKn / 4; i += 256) w4[i] = z;
        return;
    }
    unsigned sb = su32(sm);
    const __nv_bfloat16* qh = g_Qh + ((size_t)bh * TQn + q0) * DKn;
    const __nv_bfloat16* ql = g_Ql + ((size_t)bh * TQn + q0) * DKn;
    const __nv_bfloat16* kh = g_Kh + (size_t)bh * TKn * DKn;
    const __nv_bfloat16* kl = g_Kl + (size_t)bh * TKn * DKn;

    // stage Q (hi/lo) + K tile 0 as group0, K tile 1 as group1
    { int r = t >> 3, c = t & 7;
      cp16(sb + S1_QH + r * 144 + c * 16, qh + (size_t)r * 64 + c * 8);
      cp16(sb + S1_QL + r * 144 + c * 16, ql + (size_t)r * 64 + c * 8); }
    k1_stage_k(sb, kh, kl, 0, 0, t);
    k1_stage_k(sb, kh, kl, 1, 1, t);

    const int shift = g_mask_narrow ? 0 : 2;
    const unsigned char* mrow = Mb + (((size_t)bh * TKn) << shift);
    #pragma unroll
    for (int i = 0; i < 4; i++) {
        int k = t + i * 256;
        mb[k] = mrow[(size_t)k << shift] ? 0.f : MB_NEG;
    }

    // warp grid: qh_i = w>>2 (2 halves of 16 q), kq = w&3 (32-key quarter)
    const int qh_i = w >> 2, kq = w & 3;
    const int l2 = l & 15;
    const unsigned qa_h = sb + S1_QH + (16 * qh_i + (l & 15)) * 144 + (l >> 4) * 16;
    const unsigned qa_l = qa_h + (S1_QL - S1_QH);
    unsigned ah[4][4], al[4][4];

    for (int kt = 0; kt < 8; kt++) {
        int b = kt & 1;
        if (kt < 7) CPW1(); else CPW0();
        __syncthreads();
        if (kt == 0) {
            #pragma unroll
            for (int s = 0; s < 4; s++) { ldm4(ah[s], qa_h + s * 32); ldm4(al[s], qa_l + s * 32); }
        }
        unsigned kb = sb + S1_KB + b * 36864;
        #pragma unroll
        for (int nt = 0; nt < 4; nt++) {
            unsigned baddr = kb + (kq * 32 + nt * 8 + (l2 & 7)) * 144 + (l2 >> 3) * 16;
            unsigned bh_[4][2], bl_[4][2];
            #pragma unroll
            for (int s = 0; s < 4; s++) { ldm2(bh_[s], baddr + s * 32); ldm2(bl_[s], baddr + 18432 + s * 32); }
            float c[4] = {0.f, 0.f, 0.f, 0.f};
            #pragma unroll
            for (int s = 0; s < 4; s++) mma16816(c, ah[s], bh_[s]);
            #pragma unroll
            for (int s = 0; s < 4; s++) mma16816(c, ah[s], bl_[s]);
            #pragma unroll
            for (int s = 0; s < 4; s++) mma16816(c, al[s], bh_[s]);
            int g = l >> 2, j = l & 3;
            float* p = scsh + (size_t)(16 * qh_i + g) * SCST + kt * 128 + kq * 32 + nt * 8 + 2 * j;
            *(float2*)p = make_float2(c[0], c[1]);
            *(float2*)(p + 8 * SCST) = make_float2(c[2], c[3]);
        }
        __syncthreads();
        if (kt < 6) k1_stage_k(sb, kh, kl, kt + 2, b, t);
    }

    // softmax: warp w rows 4w..4w+3 (scale 1/8 + mask bias fused)
    #pragma unroll
    for (int rr = 0; rr < 4; rr++) {
        int r = 4 * w + rr;
        float* row = &scsh[(size_t)r * SCST];
        float mx = -FLT_MAX;
        #pragma unroll
        for (int i = 0; i < 8; i++) {
            float4 x = *(const float4*)&row[4 * l + 128 * i];
            float4 bq = *(const float4*)&mb[4 * l + 128 * i];
            x.x = fmaf(x.x, 0.125f, bq.x); x.y = fmaf(x.y, 0.125f, bq.y);
            x.z = fmaf(x.z, 0.125f, bq.z); x.w = fmaf(x.w, 0.125f, bq.w);
            *(float4*)&row[4 * l + 128 * i] = x;
            mx = fmaxf(mx, fmaxf(fmaxf(x.x, x.y), fmaxf(x.z, x.w)));
        }
        #pragma unroll
        for (int off = 16; off > 0; off >>= 1)
            mx = fmaxf(mx, __shfl_xor_sync(0xffffffffu, mx, off));
        float s = 0.f;
        #pragma unroll
        for (int i = 0; i < 8; i++) {
            float4 x = *(const float4*)&row[4 * l + 128 * i];
            x.x = __expf(x.x - mx); x.y = __expf(x.y - mx);
            x.z = __expf(x.z - mx); x.w = __expf(x.w - mx);
            *(float4*)&row[4 * l + 128 * i] = x;
            s += (x.x + x.y) + (x.z + x.w);
        }
        #pragma unroll
        for (int off = 16; off > 0; off >>= 1)
            s += __shfl_xor_sync(0xffffffffu, s, off);
        if (l == 0) invsh[r] = (mx == -FLT_MAX + MB_NEG || mx == -FLT_MAX) ? 0.f :
                               ((mx <= MB_NEG * 0.5f) ? 0.f : __frcp_rn(s));
    }
    __syncthreads();

    // normalized weights -> global
    {
        float4* w4 = (float4*)wbase;
        #pragma unroll
        for (int i = 0; i < 32; i++) {
            int j = t + i * 256, r = j >> 8, c4 = j & 255;
            float inv = invsh[r];
            float4 e = *(const float4*)&scsh[(size_t)r * SCST + 4 * c4];
            e.x *= inv; e.y *= inv; e.z *= inv; e.w *= inv;
            w4[r * 256 + c4] = e;
        }
    }
}

// ============ K2: O = W @ V (mma bf16 split; W split in-kernel) ============
// smem: WSH 0 + buf*18432 (hi 9216, lo +9216) | VT 36864 + buf*18432 | total 73728
#define S2_W 0
#define S2_VT 36864
#define SMEM2 73728

extern "C" __global__ void __launch_bounds__(256, 2)
attn_ov_kernel(const float* __restrict__ W, float* __restrict__ O)
{
    extern __shared__ char sm[];
    unsigned sb = su32(sm);
    const int t = threadIdx.x, w = t >> 5, l = t & 31;
    const int bh = blockIdx.y, q0 = blockIdx.x * 64;

    const float* Wb = W + ((size_t)bh * TQn + q0) * TKn;
    const __nv_bfloat16* vth = g_VTh + (size_t)bh * DKn * TKn;
    const __nv_bfloat16* vtl = g_VTl + (size_t)bh * DKn * TKn;

    // stage VT chunk kt into buffer b
    auto stage_vt = [&](int b, int kt) {
        unsigned base = sb + S2_VT + b * 18432;
        #pragma unroll
        for (int i = 0; i < 2; i++) {
            int idx = t + i * 256, r = idx >> 3, c = idx & 7;
            cp16(base + r * 144 + c * 16, vth + (size_t)r * TKn + kt * 64 + c * 8);
            cp16(base + 9216 + r * 144 + c * 16, vtl + (size_t)r * TKn + kt * 64 + c * 8);
        }
        CPC();
    };
    // load W chunk fp32 into regs
    float4 wregs[4];
    auto ldg_w = [&](int kt) {
        #pragma unroll
        for (int i = 0; i < 4; i++) {
            int idx = t + i * 256, q = idx >> 4, c4 = idx & 15;
            wregs[i] = *(const float4*)(Wb + (size_t)q * TKn + kt * 64 + c4 * 4);
        }
    };
    // split wregs and store bf16 hi/lo to wsh buffer b
    auto sts_w = [&](int b) {
        char* base = sm + S2_W + b * 18432;
        #pragma unroll
        for (int i = 0; i < 4; i++) {
            int idx = t + i * 256, q = idx >> 4, c4 = idx & 15;
            float4 x = wregs[i];
            __nv_bfloat16 h0 = __float2bfloat16(x.x), h1 = __float2bfloat16(x.y);
            __nv_bfloat16 h2 = __float2bfloat16(x.z), h3 = __float2bfloat16(x.w);
            char* d = base + q * 144 + c4 * 8;
            *(__nv_bfloat162*)d = __halves2bfloat162(h0, h1);
            *(__nv_bfloat162*)(d + 4) = __halves2bfloat162(h2, h3);
            *(__nv_bfloat162*)(d + 9216) = __halves2bfloat162(
                __float2bfloat16(x.x - __bfloat162float(h0)), __float2bfloat16(x.y - __bfloat162float(h1)));
            *(__nv_bfloat162*)(d + 9216 + 4) = __halves2bfloat162(
                __float2bfloat16(x.z - __bfloat162float(h2)), __float2bfloat16(x.w - __bfloat162float(h3)));
        }
    };

    // preamble: chunk 0
    stage_vt(0, 0);
    ldg_w(0);
    sts_w(0);
    CPW0();
    __syncthreads();

    // warp grid: qh_i = w>>1 (4 quarters of 16 q), dh = w&1 (32-d half)
    const int qh_i = w >> 1, dh = w & 1;
    const int l2 = l & 15;
    float c[4][4];
    #pragma unroll
    for (int nt = 0; nt < 4; nt++)
        #pragma unroll
        for (int i = 0; i < 4; i++) c[nt][i] = 0.f;

    for (int kt = 0; kt < 16; kt++) {
        int b = kt & 1;
        if (kt < 15) { stage_vt(b ^ 1, kt + 1); ldg_w(kt + 1); }

        unsigned wbse = sb + S2_W + b * 18432;
        unsigned vbse = sb + S2_VT + b * 18432;
        unsigned ah[4][4], al[4][4];
        #pragma unroll
        for (int s = 0; s < 4; s++) {
            unsigned a = wbse + (16 * qh_i + (l & 15)) * 144 + (l >> 4) * 16 + s * 32;
            ldm4(ah[s], a); ldm4(al[s], a + 9216);
        }
        #pragma unroll
        for (int nt = 0; nt < 4; nt++) {
            unsigned bh_[4][2], bl_[4][2];
            #pragma unroll
            for (int s = 0; s < 4; s++) {
                unsigned a = vbse + (32 * dh + nt * 8 + (l2 & 7)) * 144 + (l2 >> 3) * 16 + s * 32;
                ldm2(bh_[s], a); ldm2(bl_[s], a + 9216);
            }
            #pragma unroll
            for (int s = 0; s < 4; s++) mma16816(c[nt], ah[s], bh_[s]);
            #pragma unroll
            for (int s = 0; s < 4; s++) mma16816(c[nt], ah[s], bl_[s]);
            #pragma unroll
            for (int s = 0; s < 4; s++) mma16816(c[nt], al[s], bh_[s]);
        }

        if (kt < 15) {
            sts_w(b ^ 1);          // safe: last reads of wsh[b^1] ended before this iter's entry sync
            CPW0();
            __syncthreads();
        }
    }

    // epilogue: store O
    int g = l >> 2, j = l & 3;
    float* o0 = O + ((size_t)bh * TQn + q0 + 16 * qh_i + g) * DKn + 32 * dh;
    float* o1 = o0 + 8 * DKn;
    #pragma unroll
    for (int nt = 0; nt < 4; nt++) {
        *(float2*)(o0 + nt * 8 + 2 * j) = make_float2(c[nt][0], c[nt][1]);
        *(float2*)(o1 + nt * 8 + 2 * j) = make_float2(c[nt][2], c[nt][3]);
    }
}

// ---------------------------------------------------------------------------
extern "C" void kernel_launch(void* const* d_in, const int* in_sizes, int n_in,
                              void* d_out, int out_size) {
    const float*         Q  = (const float*)d_in[0];
    const float*         K  = (const float*)d_in[1];
    const float*         V  = (const float*)d_in[2];
    const unsigned char* Mb = (const unsigned char*)d_in[3];
    const int*           HA = (const int*)d_in[4];
    const int*           NH = (const int*)d_in[5];
    float*               O  = (float*)d_out;
    float*               W  = O + (size_t)BHn * TQn * DKn;

    cudaFuncSetAttribute(attn_qk_kernel, cudaFuncAttributeMaxDynamicSharedMemorySize, SMEM1);
    cudaFuncSetAttribute(attn_ov_kernel, cudaFuncAttributeMaxDynamicSharedMemorySize, SMEM2);

    detect_mask_kernel<<<1, 256>>>((const unsigned int*)Mb);
    split_qk_kernel<<<2048, 256>>>(Q, K);
    transpose_v_kernel<<<dim3(32, 2, 64), dim3(32, 8)>>>(V);
    attn_qk_kernel<<<dim3(32, 64), 256, SMEM1>>>(Mb, HA, NH, W);
    attn_ov_kernel<<<dim3(16, 64), 256, SMEM2>>>(W, O);
}

// round 16
// speedup vs baseline: 1.8369x; 1.1116x over previous
#include <cuda_runtime.h>
#include <cuda_bf16.h>
#include <cstdint>
#include <cfloat>

#define BHn 64
#define TQn 1024
#define TKn 1024
#define DKn 64
#define SCST 1028
#define MB_NEG -30000.0f

__device__ __nv_bfloat16 g_Qh[BHn*TQn*DKn], g_Ql[BHn*TQn*DKn];
__device__ __nv_bfloat16 g_Kh[BHn*TKn*DKn], g_Kl[BHn*TKn*DKn];
__device__ __nv_bfloat16 g_VTh[BHn*DKn*TKn], g_VTl[BHn*DKn*TKn];
__device__ int g_mask_narrow;

// ---------------- helpers ----------------
__device__ __forceinline__ unsigned su32(const void* p){ return (unsigned)__cvta_generic_to_shared(p); }
__device__ __forceinline__ void cp16(unsigned d, const void* s){ asm volatile("cp.async.cg.shared.global [%0], [%1], 16;" :: "r"(d), "l"(s)); }
#define CPC()  asm volatile("cp.async.commit_group;")
#define CPW0() asm volatile("cp.async.wait_group 0;" ::: "memory")
#define CPW1() asm volatile("cp.async.wait_group 1;" ::: "memory")

__device__ __forceinline__ void ldm4(unsigned* r, unsigned a){
    asm volatile("ldmatrix.sync.aligned.m8n8.x4.shared.b16 {%0,%1,%2,%3}, [%4];"
        : "=r"(r[0]),"=r"(r[1]),"=r"(r[2]),"=r"(r[3]) : "r"(a));
}
__device__ __forceinline__ void ldm2(unsigned* r, unsigned a){
    asm volatile("ldmatrix.sync.aligned.m8n8.x2.shared.b16 {%0,%1}, [%2];"
        : "=r"(r[0]),"=r"(r[1]) : "r"(a));
}
__device__ __forceinline__ void mma16816(float* c, const unsigned* a, const unsigned* b){
    asm volatile("mma.sync.aligned.m16n8k16.row.col.f32.bf16.bf16.f32 "
        "{%0,%1,%2,%3}, {%4,%5,%6,%7}, {%8,%9}, {%0,%1,%2,%3};"
        : "+f"(c[0]),"+f"(c[1]),"+f"(c[2]),"+f"(c[3])
        : "r"(a[0]),"r"(a[1]),"r"(a[2]),"r"(a[3]), "r"(b[0]),"r"(b[1]));
}

// ---------------- prep kernels ----------------
__global__ void detect_mask_kernel(const unsigned int* __restrict__ mw) {
    __shared__ int found;
    if (threadIdx.x == 0) found = 0;
    __syncthreads();
    int local = 0;
    for (int i = threadIdx.x; i < (BHn * TKn) / 4; i += blockDim.x)
        if (mw[i] & 0xFFFFFF00u) local = 1;
    if (local) atomicOr(&found, 1);
    __syncthreads();
    if (threadIdx.x == 0) g_mask_narrow = found;
}

__global__ void split_qk_kernel(const float* __restrict__ Q, const float* __restrict__ K) {
    int n = BHn * TQn * DKn;
    for (int i = blockIdx.x * blockDim.x + threadIdx.x; i < n; i += gridDim.x * blockDim.x) {
        float q = Q[i]; __nv_bfloat16 h = __float2bfloat16(q);
        g_Qh[i] = h; g_Ql[i] = __float2bfloat16(q - __bfloat162float(h));
        float k = K[i]; h = __float2bfloat16(k);
        g_Kh[i] = h; g_Kl[i] = __float2bfloat16(k - __bfloat162float(h));
    }
}

__global__ void transpose_v_kernel(const float* __restrict__ V) {
    __shared__ float tile[32][33];
    int bh = blockIdx.z, k0 = blockIdx.x * 32, d0 = blockIdx.y * 32;
    const float* Vb = V + (size_t)bh * TKn * DKn;
    for (int r = threadIdx.y; r < 32; r += 8)
        tile[r][threadIdx.x] = Vb[(size_t)(k0 + r) * DKn + d0 + threadIdx.x];
    __syncthreads();
    for (int r = threadIdx.y; r < 32; r += 8) {
        float v = tile[threadIdx.x][r];
        __nv_bfloat16 h = __float2bfloat16(v);
        size_t o = (size_t)bh * DKn * TKn + (size_t)(d0 + r) * TKn + k0 + threadIdx.x;
        g_VTh[o] = h; g_VTl[o] = __float2bfloat16(v - __bfloat162float(h));
    }
}

// ============ K1: e = exp(QK/8 + maskbias) fused in MMA epilogue ============
// smem: QH 0 (4608) | QL 4608 | K 9216 + buf*36864 | SC 82944 (131584)
//       MB 214528 (4096) | PART 218624 (1024) | INV 219648 (128) -> 219776
#define S1_QH 0
#define S1_QL 4608
#define S1_KB 9216
#define S1_SC 82944
#define S1_MB 214528
#define S1_PART 218624
#define S1_INV 219648
#define SMEM1 219776
#define NT1 512

__device__ __forceinline__ void k1_stage_k(unsigned sb, const __nv_bfloat16* kh,
                                           const __nv_bfloat16* kl, int kt, int buf, int t) {
    unsigned base = sb + S1_KB + buf * 36864;
    const __nv_bfloat16* sh = kh + (size_t)kt * 128 * 64;
    const __nv_bfloat16* sl = kl + (size_t)kt * 128 * 64;
    #pragma unroll
    for (int i = 0; i < 2; i++) {
        int idx = t + i * NT1, r = idx >> 3, c = idx & 7;
        cp16(base + r * 144 + c * 16, sh + (size_t)r * 64 + c * 8);
        cp16(base + 18432 + r * 144 + c * 16, sl + (size_t)r * 64 + c * 8);
    }
    CPC();
}

extern "C" __global__ void __launch_bounds__(NT1, 1)
attn_qk_kernel(const unsigned char* __restrict__ Mb, const int* __restrict__ pHA,
               const int* __restrict__ pNH, float* __restrict__ Wout)
{
    extern __shared__ char sm[];
    float* scsh  = (float*)(sm + S1_SC);
    float* mb    = (float*)(sm + S1_MB);
    float* part  = (float*)(sm + S1_PART);
    float* invsh = (float*)(sm + S1_INV);

    const int t = threadIdx.x, w = t >> 5, l = t & 31;
    const int bh = blockIdx.y, q0 = blockIdx.x * 32;
    float* wbase = Wout + ((size_t)bh * TQn + q0) * TKn;

    if (pNH[0] > 0 && (bh % pNH[0]) == pHA[0]) {
        float4 z = make_float4(0.f, 0.f, 0.f, 0.f);
        float4* w4 = (float4*)wbase;
        #pragma unroll 4
        for (int i = t; i < 32 * TKn / 4; i += NT1) w4[i] = z;
        return;
    }
    unsigned sb = su32(sm);
    const __nv_bfloat16* qh = g_Qh + ((size_t)bh * TQn + q0) * DKn;
    const __nv_bfloat16* ql = g_Ql + ((size_t)bh * TQn + q0) * DKn;
    const __nv_bfloat16* kh = g_Kh + (size_t)bh * TKn * DKn;
    const __nv_bfloat16* kl = g_Kl + (size_t)bh * TKn * DKn;

    if (t < 256) {
        int r = t >> 3, c = t & 7;
        cp16(sb + S1_QH + r * 144 + c * 16, qh + (size_t)r * 64 + c * 8);
        cp16(sb + S1_QL + r * 144 + c * 16, ql + (size_t)r * 64 + c * 8);
    }
    k1_stage_k(sb, kh, kl, 0, 0, t);
    k1_stage_k(sb, kh, kl, 1, 1, t);

    const int shift = g_mask_narrow ? 0 : 2;
    const unsigned char* mrow = Mb + (((size_t)bh * TKn) << shift);
    #pragma unroll
    for (int i = 0; i < 2; i++) {
        int k = t + i * NT1;
        mb[k] = mrow[(size_t)k << shift] ? 0.f : MB_NEG;
    }

    // warp grid: qhx = w>>3 (2 halves of 16 q), ks = w&7 (16-key sixteenth)
    const int qhx = w >> 3, ks = w & 7;
    const int l2 = l & 15, g = l >> 2, j = l & 3;
    const unsigned qa_h = sb + S1_QH + (16 * qhx + (l & 15)) * 144 + (l >> 4) * 16;
    const unsigned qa_l = qa_h + (S1_QL - S1_QH);
    unsigned ah[4][4], al[4][4];
    float s_lo = 0.f, s_hi = 0.f;

    for (int kt = 0; kt < 8; kt++) {
        int b = kt & 1;
        if (kt < 7) CPW1(); else CPW0();
        __syncthreads();
        if (kt == 0) {
            #pragma unroll
            for (int s = 0; s < 4; s++) { ldm4(ah[s], qa_h + s * 32); ldm4(al[s], qa_l + s * 32); }
        }
        unsigned kb = sb + S1_KB + b * 36864;
        #pragma unroll
        for (int nt = 0; nt < 2; nt++) {
            unsigned baddr = kb + (ks * 16 + nt * 8 + (l2 & 7)) * 144 + (l2 >> 3) * 16;
            unsigned bh_[4][2], bl_[4][2];
            #pragma unroll
            for (int s = 0; s < 4; s++) { ldm2(bh_[s], baddr + s * 32); ldm2(bl_[s], baddr + 18432 + s * 32); }
            float c[4] = {0.f, 0.f, 0.f, 0.f};
            #pragma unroll
            for (int s = 0; s < 4; s++) mma16816(c, ah[s], bh_[s]);
            #pragma unroll
            for (int s = 0; s < 4; s++) mma16816(c, ah[s], bl_[s]);
            #pragma unroll
            for (int s = 0; s < 4; s++) mma16816(c, al[s], bh_[s]);
            // fused epilogue: exp(s/8 + maskbias), accumulate row sums
            int kloc = kt * 128 + ks * 16 + nt * 8 + 2 * j;
            float2 mbv = *(const float2*)&mb[kloc];
            float e00 = __expf(fmaf(c[0], 0.125f, mbv.x));
            float e01 = __expf(fmaf(c[1], 0.125f, mbv.y));
            float e10 = __expf(fmaf(c[2], 0.125f, mbv.x));
            float e11 = __expf(fmaf(c[3], 0.125f, mbv.y));
            s_lo += e00 + e01; s_hi += e10 + e11;
            float* p = scsh + (size_t)(16 * qhx + g) * SCST + kloc;
            *(float2*)p = make_float2(e00, e01);
            *(float2*)(p + 8 * SCST) = make_float2(e10, e11);
        }
        __syncthreads();
        if (kt < 6) k1_stage_k(sb, kh, kl, kt + 2, b, t);
    }

    // row-sum reduce: over j lanes, then across the 8 ks warps via smem
    s_lo += __shfl_xor_sync(0xffffffffu, s_lo, 1);
    s_lo += __shfl_xor_sync(0xffffffffu, s_lo, 2);
    s_hi += __shfl_xor_sync(0xffffffffu, s_hi, 1);
    s_hi += __shfl_xor_sync(0xffffffffu, s_hi, 2);
    if (j == 0) {
        part[w * 16 + g] = s_lo;
        part[w * 16 + 8 + g] = s_hi;
    }
    __syncthreads();
    if (t < 32) {
        int qhh = t >> 4, g2 = t & 15;
        float s = 0.f;
        #pragma unroll
        for (int k2 = 0; k2 < 8; k2++) s += part[(qhh * 8 + k2) * 16 + g2];
        invsh[t] = (s == 0.f) ? 0.f : __frcp_rn(s);
    }
    __syncthreads();

    // normalized weights -> global
    {
        float4* w4 = (float4*)wbase;
        #pragma unroll
        for (int i = 0; i < 16; i++) {
            int jj = t + i * NT1, r = jj >> 8, c4 = jj & 255;
            float inv = invsh[r];
            float4 e = *(const float4*)&scsh[(size_t)r * SCST + 4 * c4];
            e.x *= inv; e.y *= inv; e.z *= inv; e.w *= inv;
            w4[r * 256 + c4] = e;
        }
    }
}

// ============ K2: O = W @ V (mma bf16 split; W split in-kernel) ============
#define S2_W 0
#define S2_VT 36864
#define SMEM2 73728

extern "C" __global__ void __launch_bounds__(256, 2)
attn_ov_kernel(const float* __restrict__ W, float* __restrict__ O)
{
    extern __shared__ char sm[];
    unsigned sb = su32(sm);
    const int t = threadIdx.x, w = t >> 5, l = t & 31;
    const int bh = blockIdx.y, q0 = blockIdx.x * 64;

    const float* Wb = W + ((size_t)bh * TQn + q0) * TKn;
    const __nv_bfloat16* vth = g_VTh + (size_t)bh * DKn * TKn;
    const __nv_bfloat16* vtl = g_VTl + (size_t)bh * DKn * TKn;

    auto stage_vt = [&](int b, int kt) {
        unsigned base = sb + S2_VT + b * 18432;
        #pragma unroll
        for (int i = 0; i < 2; i++) {
            int idx = t + i * 256, r = idx >> 3, c = idx & 7;
            cp16(base + r * 144 + c * 16, vth + (size_t)r * TKn + kt * 64 + c * 8);
            cp16(base + 9216 + r * 144 + c * 16, vtl + (size_t)r * TKn + kt * 64 + c * 8);
        }
        CPC();
    };
    float4 wregs[4];
    auto ldg_w = [&](int kt) {
        #pragma unroll
        for (int i = 0; i < 4; i++) {
            int idx = t + i * 256, q = idx >> 4, c4 = idx & 15;
            wregs[i] = *(const float4*)(Wb + (size_t)q * TKn + kt * 64 + c4 * 4);
        }
    };
    auto sts_w = [&](int b) {
        char* base = sm + S2_W + b * 18432;
        #pragma unroll
        for (int i = 0; i < 4; i++) {
            int idx = t + i * 256, q = idx >> 4, c4 = idx & 15;
            float4 x = wregs[i];
            __nv_bfloat16 h0 = __float2bfloat16(x.x), h1 = __float2bfloat16(x.y);
            __nv_bfloat16 h2 = __float2bfloat16(x.z), h3 = __float2bfloat16(x.w);
            char* d = base + q * 144 + c4 * 8;
            *(__nv_bfloat162*)d = __halves2bfloat162(h0, h1);
            *(__nv_bfloat162*)(d + 4) = __halves2bfloat162(h2, h3);
            *(__nv_bfloat162*)(d + 9216) = __halves2bfloat162(
                __float2bfloat16(x.x - __bfloat162float(h0)), __float2bfloat16(x.y - __bfloat162float(h1)));
            *(__nv_bfloat162*)(d + 9216 + 4) = __halves2bfloat162(
                __float2bfloat16(x.z - __bfloat162float(h2)), __float2bfloat16(x.w - __bfloat162float(h3)));
        }
    };

    stage_vt(0, 0);
    ldg_w(0);
    sts_w(0);
    CPW0();
    __syncthreads();

    const int qh_i = w >> 1, dh = w & 1;
    const int l2 = l & 15;
    float c[4][4];
    #pragma unroll
    for (int nt = 0; nt < 4; nt++)
        #pragma unroll
        for (int i = 0; i < 4; i++) c[nt][i] = 0.f;

    for (int kt = 0; kt < 16; kt++) {
        int b = kt & 1;
        if (kt < 15) { stage_vt(b ^ 1, kt + 1); ldg_w(kt + 1); }

        unsigned wbse = sb + S2_W + b * 18432;
        unsigned vbse = sb + S2_VT + b * 18432;
        unsigned ah[4][4], al[4][4];
        #pragma unroll
        for (int s = 0; s < 4; s++) {
            unsigned a = wbse + (16 * qh_i + (l & 15)) * 144 + (l >> 4) * 16 + s * 32;
            ldm4(ah[s], a); ldm4(al[s], a + 9216);
        }
        #pragma unroll
        for (int nt = 0; nt < 4; nt++) {
            unsigned bh_[4][2], bl_[4][2];
            #pragma unroll
            for (int s = 0; s < 4; s++) {
                unsigned a = vbse + (32 * dh + nt * 8 + (l2 & 7)) * 144 + (l2 >> 3) * 16 + s * 32;
                ldm2(bh_[s], a); ldm2(bl_[s], a + 9216);
            }
            #pragma unroll
            for (int s = 0; s < 4; s++) mma16816(c[nt], ah[s], bh_[s]);
            #pragma unroll
            for (int s = 0; s < 4; s++) mma16816(c[nt], ah[s], bl_[s]);
            #pragma unroll
            for (int s = 0; s < 4; s++) mma16816(c[nt], al[s], bh_[s]);
        }

        if (kt < 15) {
            sts_w(b ^ 1);
            CPW0();
            __syncthreads();
        }
    }

    int g = l >> 2, j = l & 3;
    float* o0 = O + ((size_t)bh * TQn + q0 + 16 * qh_i + g) * DKn + 32 * dh;
    float* o1 = o0 + 8 * DKn;
    #pragma unroll
    for (int nt = 0; nt < 4; nt++) {
        *(float2*)(o0 + nt * 8 + 2 * j) = make_float2(c[nt][0], c[nt][1]);
        *(float2*)(o1 + nt * 8 + 2 * j) = make_float2(c[nt][2], c[nt][3]);
    }
}

// ---------------------------------------------------------------------------
extern "C" void kernel_launch(void* const* d_in, const int* in_sizes, int n_in,
                              void* d_out, int out_size) {
    const float*         Q  = (const float*)d_in[0];
    const float*         K  = (const float*)d_in[1];
    const float*         V  = (const float*)d_in[2];
    const unsigned char* Mb = (const unsigned char*)d_in[3];
    const int*           HA = (const int*)d_in[4];
    const int*           NH = (const int*)d_in[5];
    float*               O  = (float*)d_out;
    float*               W  = O + (size_t)BHn * TQn * DKn;

    cudaFuncSetAttribute(attn_qk_kernel, cudaFuncAttributeMaxDynamicSharedMemorySize, SMEM1);
    cudaFuncSetAttribute(attn_ov_kernel, cudaFuncAttributeMaxDynamicSharedMemorySize, SMEM2);

    detect_mask_kernel<<<1, 256>>>((const unsigned int*)Mb);
    split_qk_kernel<<<2048, 256>>>(Q, K);
    transpose_v_kernel<<<dim3(32, 2, 64), dim3(32, 8)>>>(V);
    attn_qk_kernel<<<dim3(32, 64), NT1, SMEM1>>>(Mb, HA, NH, W);
    attn_ov_kernel<<<dim3(16, 64), 256, SMEM2>>>(W, O);
}